// round 14
// baseline (speedup 1.0000x reference)
#include <cuda_runtime.h>
#include <cuda_bf16.h>
#include <cstdint>
#include <math.h>

// Problem constants
#define S_LEN 2048
#define E_DIM 1024
#define NH    16
#define DKH   64
#define BATCH 2
#define M_TOT (BATCH * S_LEN)   // 4096

// Scratch
__device__ float g_Q[BATCH * NH * S_LEN * DKH];   // [B,H,S,DK]
__device__ float g_K[BATCH * NH * S_LEN * DKH];
__device__ float g_V[BATCH * NH * S_LEN * DKH];
__device__ float g_X[M_TOT * E_DIM];              // attention out, [B,S,E]

// ---------------------------------------------------------------------------
// Warp-level bf16 MMA (base sm_100 ISA).
// ---------------------------------------------------------------------------
__device__ __forceinline__ void mma16816(float* c, const uint32_t* a, const uint32_t* b) {
    asm volatile(
        "mma.sync.aligned.m16n8k16.row.col.f32.bf16.bf16.f32 "
        "{%0,%1,%2,%3}, {%4,%5,%6,%7}, {%8,%9}, {%0,%1,%2,%3};"
        : "+f"(c[0]), "+f"(c[1]), "+f"(c[2]), "+f"(c[3])
        : "r"(a[0]), "r"(a[1]), "r"(a[2]), "r"(a[3]), "r"(b[0]), "r"(b[1]));
}

__device__ __forceinline__ void split2(float x, float y, uint32_t& hi, uint32_t& lo) {
    __nv_bfloat16 hx = __float2bfloat16_rn(x);
    __nv_bfloat16 hy = __float2bfloat16_rn(y);
    __nv_bfloat16 lx = __float2bfloat16_rn(x - __bfloat162float(hx));
    __nv_bfloat16 ly = __float2bfloat16_rn(y - __bfloat162float(hy));
    hi = (uint32_t)__bfloat16_as_ushort(hx) | ((uint32_t)__bfloat16_as_ushort(hy) << 16);
    lo = (uint32_t)__bfloat16_as_ushort(lx) | ((uint32_t)__bfloat16_as_ushort(ly) << 16);
}

// ---------------------------------------------------------------------------
// GEMM: Y = X @ W^T + bias via HMMA bf16 hi/lo 3-pass.
// qkv3 mode: blockIdx.z in {0,1,2} selects (X,W,bias,Y) triple (fused QKV).
// ---------------------------------------------------------------------------
#define PITCH 20

__global__ __launch_bounds__(256) void gemm_mma_kernel(
    const float* __restrict__ X0p, const float* __restrict__ W0p,
    const float* __restrict__ b0p, float* __restrict__ Y0p,
    const float* __restrict__ X1p, const float* __restrict__ W1p,
    const float* __restrict__ b1p, float* __restrict__ Y1p,
    const float* __restrict__ X2p, const float* __restrict__ W2p,
    const float* __restrict__ b2p, float* __restrict__ Y2p,
    int splitHeads)
{
    __shared__ uint32_t Ahi[128][PITCH];
    __shared__ uint32_t Alo[128][PITCH];
    __shared__ uint32_t Bhi[128][PITCH];
    __shared__ uint32_t Blo[128][PITCH];

    const int z = blockIdx.z;
    const float* X    = (z == 0) ? X0p : (z == 1) ? X1p : X2p;
    const float* W    = (z == 0) ? W0p : (z == 1) ? W1p : W2p;
    const float* bias = (z == 0) ? b0p : (z == 1) ? b1p : b2p;
    float*       Y    = (z == 0) ? Y0p : (z == 1) ? Y1p : Y2p;

    const int tid  = threadIdx.x;
    const int warp = tid >> 5;
    const int lane = tid & 31;
    const int g = lane >> 2;
    const int t = lane & 3;
    const int wm = warp >> 2;
    const int wn = warp & 3;
    const int m0 = blockIdx.y * 128;
    const int n0 = blockIdx.x * 128;

    float acc[4][4][4];
    #pragma unroll
    for (int i = 0; i < 4; i++)
        #pragma unroll
        for (int j = 0; j < 4; j++)
            #pragma unroll
            for (int r = 0; r < 4; r++) acc[i][j][r] = 0.f;

    for (int kc = 0; kc < E_DIM / 32; kc++) {
        const int kt = kc * 32;
        #pragma unroll
        for (int i = 0; i < 4; i++) {
            const int f   = tid + i * 256;
            const int row = f >> 3;
            const int cb  = f & 7;
            const float4 xv = *(const float4*)(X + (size_t)(m0 + row) * E_DIM + kt + cb * 4);
            const float4 wv = *(const float4*)(W + (size_t)(n0 + row) * E_DIM + kt + cb * 4);
            uint32_t h0, l0, h1, l1;
            split2(xv.x, xv.y, h0, l0);
            split2(xv.z, xv.w, h1, l1);
            Ahi[row][cb * 2] = h0; Ahi[row][cb * 2 + 1] = h1;
            Alo[row][cb * 2] = l0; Alo[row][cb * 2 + 1] = l1;
            split2(wv.x, wv.y, h0, l0);
            split2(wv.z, wv.w, h1, l1);
            Bhi[row][cb * 2] = h0; Bhi[row][cb * 2 + 1] = h1;
            Blo[row][cb * 2] = l0; Blo[row][cb * 2 + 1] = l1;
        }
        __syncthreads();

        #pragma unroll
        for (int ks = 0; ks < 2; ks++) {
            const int kb = ks * 8;
            uint32_t ah[4][4], al[4][4], bh[4][2], bl[4][2];
            #pragma unroll
            for (int mi = 0; mi < 4; mi++) {
                const int r = wm * 64 + mi * 16 + g;
                ah[mi][0] = Ahi[r][kb + t];     ah[mi][1] = Ahi[r + 8][kb + t];
                ah[mi][2] = Ahi[r][kb + t + 4]; ah[mi][3] = Ahi[r + 8][kb + t + 4];
                al[mi][0] = Alo[r][kb + t];     al[mi][1] = Alo[r + 8][kb + t];
                al[mi][2] = Alo[r][kb + t + 4]; al[mi][3] = Alo[r + 8][kb + t + 4];
            }
            #pragma unroll
            for (int ni = 0; ni < 4; ni++) {
                const int r = wn * 32 + ni * 8 + g;
                bh[ni][0] = Bhi[r][kb + t]; bh[ni][1] = Bhi[r][kb + t + 4];
                bl[ni][0] = Blo[r][kb + t]; bl[ni][1] = Blo[r][kb + t + 4];
            }
            #pragma unroll
            for (int mi = 0; mi < 4; mi++)
                #pragma unroll
                for (int ni = 0; ni < 4; ni++) {
                    mma16816(acc[mi][ni], ah[mi], bh[ni]);
                    mma16816(acc[mi][ni], ah[mi], bl[ni]);
                    mma16816(acc[mi][ni], al[mi], bh[ni]);
                }
        }
        __syncthreads();
    }

    #pragma unroll
    for (int mi = 0; mi < 4; mi++) {
        const int mlo = m0 + wm * 64 + mi * 16 + g;
        const int mhi = mlo + 8;
        #pragma unroll
        for (int ni = 0; ni < 4; ni++) {
            const int nb = n0 + wn * 32 + ni * 8 + 2 * t;
            const float bv0 = bias[nb], bv1 = bias[nb + 1];
            const float v00 = acc[mi][ni][0] + bv0;
            const float v01 = acc[mi][ni][1] + bv1;
            const float v10 = acc[mi][ni][2] + bv0;
            const float v11 = acc[mi][ni][3] + bv1;
            if (splitHeads) {
                const int b0 = mlo >> 11, s0 = mlo & (S_LEN - 1);
                const int b1 = mhi >> 11, s1 = mhi & (S_LEN - 1);
                const int h0 = nb >> 6, d0 = nb & 63;
                const int h1 = (nb + 1) >> 6, d1 = (nb + 1) & 63;
                Y[((size_t)((b0 * NH + h0) * S_LEN + s0)) * DKH + d0] = v00;
                Y[((size_t)((b0 * NH + h1) * S_LEN + s0)) * DKH + d1] = v01;
                Y[((size_t)((b1 * NH + h0) * S_LEN + s1)) * DKH + d0] = v10;
                Y[((size_t)((b1 * NH + h1) * S_LEN + s1)) * DKH + d1] = v11;
            } else {
                Y[(size_t)mlo * E_DIM + nb]     = v00;
                Y[(size_t)mlo * E_DIM + nb + 1] = v01;
                Y[(size_t)mhi * E_DIM + nb]     = v10;
                Y[(size_t)mhi * E_DIM + nb + 1] = v11;
            }
        }
    }
}

// ---------------------------------------------------------------------------
// Flash attention via HMMA. BQ=128 (8 warps x 16 rows), BKV=64, causal.
// __launch_bounds__(256, 2): cap regs at 128 for 2 CTAs/SM (occ 25%).
// PV loop ks-outer: only 8 live P-fragment regs (was 32).
// ---------------------------------------------------------------------------
#define FPITCH 36
#define FS_QHI 0
#define FS_QLO 4608
#define FS_KHI 9216
#define FS_KLO 11520
#define FS_VHI 13824
#define FS_VLO 16128
#define FS_TOTAL_B32 18432   // 73728 bytes

__global__ __launch_bounds__(256, 2) void flash_mma_kernel()
{
    extern __shared__ uint32_t fsm[];
    uint32_t (*Qhi)[FPITCH]  = (uint32_t(*)[FPITCH])(fsm + FS_QHI);
    uint32_t (*Qlo)[FPITCH]  = (uint32_t(*)[FPITCH])(fsm + FS_QLO);
    uint32_t (*Khi)[FPITCH]  = (uint32_t(*)[FPITCH])(fsm + FS_KHI);
    uint32_t (*Klo)[FPITCH]  = (uint32_t(*)[FPITCH])(fsm + FS_KLO);
    uint32_t (*Vthi)[FPITCH] = (uint32_t(*)[FPITCH])(fsm + FS_VHI);
    uint32_t (*Vtlo)[FPITCH] = (uint32_t(*)[FPITCH])(fsm + FS_VLO);

    const int tid  = threadIdx.x;
    const int warp = tid >> 5;
    const int lane = tid & 31;
    const int g = lane >> 2;
    const int t = lane & 3;
    const int qt = (int)gridDim.x - 1 - (int)blockIdx.x;  // big tiles first
    const int bh = blockIdx.y;
    const int b  = bh >> 4;
    const int h  = bh & 15;

    const float* Qg = g_Q + (size_t)bh * S_LEN * DKH + (size_t)qt * 128 * DKH;
    const float* Kg = g_K + (size_t)bh * S_LEN * DKH;
    const float* Vg = g_V + (size_t)bh * S_LEN * DKH;

    // Load Q strip (128 x 64): 2048 float4 over 256 threads
    #pragma unroll
    for (int i = 0; i < 8; i++) {
        const int f = tid + i * 256;
        const int r = f >> 4, c4 = f & 15;
        const float4 qv = *(const float4*)(Qg + (size_t)r * DKH + c4 * 4);
        uint32_t h0, l0, h1, l1;
        split2(qv.x, qv.y, h0, l0);
        split2(qv.z, qv.w, h1, l1);
        Qhi[r][2 * c4] = h0; Qhi[r][2 * c4 + 1] = h1;
        Qlo[r][2 * c4] = l0; Qlo[r][2 * c4 + 1] = l1;
    }

    float o[8][4];
    #pragma unroll
    for (int nj = 0; nj < 8; nj++)
        #pragma unroll
        for (int r = 0; r < 4; r++) o[nj][r] = 0.f;
    float m0 = -1e30f, m1 = -1e30f, l0s = 0.f, l1s = 0.f;

    const int ntiles = 2 * qt + 2;
    for (int kt = 0; kt < ntiles; kt++) {
        const int kv0 = kt * 64;

        // K tile (64 x 64) -> Khi/Klo [kv][d-pairs]
        #pragma unroll
        for (int i = 0; i < 4; i++) {
            const int f = tid + i * 256;
            const int r = f >> 4, c4 = f & 15;
            const float4 kv4 = *(const float4*)(Kg + (size_t)(kv0 + r) * DKH + c4 * 4);
            uint32_t h0, l0, h1, l1;
            split2(kv4.x, kv4.y, h0, l0);
            split2(kv4.z, kv4.w, h1, l1);
            Khi[r][2 * c4] = h0; Khi[r][2 * c4 + 1] = h1;
            Klo[r][2 * c4] = l0; Klo[r][2 * c4 + 1] = l1;
        }
        // V tile transposed -> Vthi/Vtlo [d][kv-pairs]
        #pragma unroll
        for (int i = 0; i < 2; i++) {
            const int f = tid + i * 256;
            const int kv2 = f & 31, d4 = f >> 5;
            const float* vp = Vg + (size_t)(kv0 + 2 * kv2) * DKH + d4 * 4;
            const float4 va = *(const float4*)(vp);
            const float4 vb = *(const float4*)(vp + DKH);
            const float aa[4] = {va.x, va.y, va.z, va.w};
            const float bb[4] = {vb.x, vb.y, vb.z, vb.w};
            #pragma unroll
            for (int dd = 0; dd < 4; dd++) {
                uint32_t hh, ll;
                split2(aa[dd], bb[dd], hh, ll);
                Vthi[d4 * 4 + dd][kv2] = hh;
                Vtlo[d4 * 4 + dd][kv2] = ll;
            }
        }
        __syncthreads();

        // ---- S = Q K^T over all 64 kv columns, 3-pass hi/lo ----
        float sv[8][4];
        #pragma unroll
        for (int ni = 0; ni < 8; ni++)
            #pragma unroll
            for (int j = 0; j < 4; j++) sv[ni][j] = 0.f;

        const int r0 = warp * 16 + g;
        #pragma unroll
        for (int ks = 0; ks < 4; ks++) {
            const int kb = 8 * ks;
            uint32_t aqh[4], aql[4];
            aqh[0] = Qhi[r0][kb + t];     aqh[1] = Qhi[r0 + 8][kb + t];
            aqh[2] = Qhi[r0][kb + t + 4]; aqh[3] = Qhi[r0 + 8][kb + t + 4];
            aql[0] = Qlo[r0][kb + t];     aql[1] = Qlo[r0 + 8][kb + t];
            aql[2] = Qlo[r0][kb + t + 4]; aql[3] = Qlo[r0 + 8][kb + t + 4];
            #pragma unroll
            for (int ni = 0; ni < 8; ni++) {
                uint32_t bkh[2], bkl[2];
                const int kr = 8 * ni + g;
                bkh[0] = Khi[kr][kb + t]; bkh[1] = Khi[kr][kb + t + 4];
                bkl[0] = Klo[kr][kb + t]; bkl[1] = Klo[kr][kb + t + 4];
                mma16816(sv[ni], aqh, bkh);
                mma16816(sv[ni], aqh, bkl);
                mma16816(sv[ni], aql, bkh);
            }
        }

        // ---- softmax (online) ----
        const bool dm = (kt >= 2 * qt);
        const int cb = (kt - 2 * qt) * 64;
        float mx0 = -1e30f, mx1 = -1e30f;
        #pragma unroll
        for (int ni = 0; ni < 8; ni++) {
            #pragma unroll
            for (int j = 0; j < 4; j++) {
                float s = sv[ni][j] * 0.125f;
                if (dm) {
                    const int c = cb + 8 * ni + 2 * t + (j & 1);
                    const int r = (j < 2) ? r0 : (r0 + 8);
                    if (c > r) s = -1e30f;
                }
                sv[ni][j] = s;
            }
            mx0 = fmaxf(mx0, fmaxf(sv[ni][0], sv[ni][1]));
            mx1 = fmaxf(mx1, fmaxf(sv[ni][2], sv[ni][3]));
        }
        mx0 = fmaxf(mx0, __shfl_xor_sync(0xffffffffu, mx0, 1));
        mx0 = fmaxf(mx0, __shfl_xor_sync(0xffffffffu, mx0, 2));
        mx1 = fmaxf(mx1, __shfl_xor_sync(0xffffffffu, mx1, 1));
        mx1 = fmaxf(mx1, __shfl_xor_sync(0xffffffffu, mx1, 2));

        const float m0n = fmaxf(m0, mx0);
        const float m1n = fmaxf(m1, mx1);
        const float a0 = __expf(m0 - m0n);
        const float a1 = __expf(m1 - m1n);
        float rs0 = 0.f, rs1 = 0.f;
        #pragma unroll
        for (int ni = 0; ni < 8; ni++) {
            sv[ni][0] = __expf(sv[ni][0] - m0n);
            sv[ni][1] = __expf(sv[ni][1] - m0n);
            sv[ni][2] = __expf(sv[ni][2] - m1n);
            sv[ni][3] = __expf(sv[ni][3] - m1n);
            rs0 += sv[ni][0] + sv[ni][1];
            rs1 += sv[ni][2] + sv[ni][3];
        }
        rs0 += __shfl_xor_sync(0xffffffffu, rs0, 1);
        rs0 += __shfl_xor_sync(0xffffffffu, rs0, 2);
        rs1 += __shfl_xor_sync(0xffffffffu, rs1, 1);
        rs1 += __shfl_xor_sync(0xffffffffu, rs1, 2);
        l0s = l0s * a0 + rs0;
        l1s = l1s * a1 + rs1;
        m0 = m0n; m1 = m1n;
        #pragma unroll
        for (int nj = 0; nj < 8; nj++) {
            o[nj][0] *= a0; o[nj][1] *= a0;
            o[nj][2] *= a1; o[nj][3] *= a1;
        }

        // ---- O += P V, ks-outer (only 8 live P-frag regs) ----
        #pragma unroll
        for (int ks = 0; ks < 4; ks++) {
            uint32_t aph[4], apl[4];
            split2(sv[2*ks][0],   sv[2*ks][1],   aph[0], apl[0]);
            split2(sv[2*ks][2],   sv[2*ks][3],   aph[1], apl[1]);
            split2(sv[2*ks+1][0], sv[2*ks+1][1], aph[2], apl[2]);
            split2(sv[2*ks+1][2], sv[2*ks+1][3], aph[3], apl[3]);
            const int kb = 8 * ks;
            #pragma unroll
            for (int nj = 0; nj < 8; nj++) {
                const int vr = 8 * nj + g;
                uint32_t bvh[2], bvl[2];
                bvh[0] = Vthi[vr][kb + t]; bvh[1] = Vthi[vr][kb + t + 4];
                bvl[0] = Vtlo[vr][kb + t]; bvl[1] = Vtlo[vr][kb + t + 4];
                mma16816(o[nj], aph, bvh);
                mma16816(o[nj], aph, bvl);
                mma16816(o[nj], apl, bvh);
            }
        }
        __syncthreads();
    }

    // ---- epilogue: O / l -> g_X [B,S,E] ----
    const float i0 = 1.f / l0s;
    const float i1 = 1.f / l1s;
    const int s0 = qt * 128 + warp * 16 + g;
    float* X0 = g_X + ((size_t)(b * S_LEN + s0)) * E_DIM + h * DKH;
    float* X1 = X0 + 8 * E_DIM;
    #pragma unroll
    for (int nj = 0; nj < 8; nj++) {
        const int d = 8 * nj + 2 * t;
        *(float2*)(X0 + d) = make_float2(o[nj][0] * i0, o[nj][1] * i0);
        *(float2*)(X1 + d) = make_float2(o[nj][2] * i1, o[nj][3] * i1);
    }
}

// ---------------------------------------------------------------------------
extern "C" void kernel_launch(void* const* d_in, const int* in_sizes, int n_in,
                              void* d_out, int out_size)
{
    const float *q, *k, *v, *wq, *bq, *wk, *bk, *wv, *bv, *wo, *bo;
    if (in_sizes[0] == 1024) {
        // alphabetical: bk bo bq bv key_ mask query value wk wo wq wv
        bk = (const float*)d_in[0];
        bo = (const float*)d_in[1];
        bq = (const float*)d_in[2];
        bv = (const float*)d_in[3];
        k  = (const float*)d_in[4];
        q  = (const float*)d_in[6];
        v  = (const float*)d_in[7];
        wk = (const float*)d_in[8];
        wo = (const float*)d_in[9];
        wq = (const float*)d_in[10];
        wv = (const float*)d_in[11];
    } else {
        // insertion order
        q  = (const float*)d_in[0];
        k  = (const float*)d_in[1];
        v  = (const float*)d_in[2];
        wq = (const float*)d_in[4];
        bq = (const float*)d_in[5];
        wk = (const float*)d_in[6];
        bk = (const float*)d_in[7];
        wv = (const float*)d_in[8];
        bv = (const float*)d_in[9];
        wo = (const float*)d_in[10];
        bo = (const float*)d_in[11];
    }

    float *pQ, *pK, *pV, *pX;
    cudaGetSymbolAddress((void**)&pQ, g_Q);
    cudaGetSymbolAddress((void**)&pK, g_K);
    cudaGetSymbolAddress((void**)&pV, g_V);
    cudaGetSymbolAddress((void**)&pX, g_X);

    const int flash_smem = FS_TOTAL_B32 * (int)sizeof(uint32_t); // 73728
    cudaFuncSetAttribute(flash_mma_kernel,
                         cudaFuncAttributeMaxDynamicSharedMemorySize, flash_smem);

    // Fused QKV projections: grid z selects operand set
    dim3 gqkv(E_DIM / 128, M_TOT / 128, 3);
    gemm_mma_kernel<<<gqkv, 256>>>(q, wq, bq, pQ,
                                   k, wk, bk, pK,
                                   v, wv, bv, pV, 1);

    flash_mma_kernel<<<dim3(S_LEN / 128, BATCH * NH), 256, flash_smem>>>();

    dim3 go(E_DIM / 128, M_TOT / 128, 1);
    gemm_mma_kernel<<<go, 256>>>(pX, wo, bo, (float*)d_out,
                                 pX, wo, bo, (float*)d_out,
                                 pX, wo, bo, (float*)d_out, 0);
}

// round 15
// speedup vs baseline: 1.1499x; 1.1499x over previous
#include <cuda_runtime.h>
#include <cuda_bf16.h>
#include <cstdint>
#include <math.h>

// Problem constants
#define S_LEN 2048
#define E_DIM 1024
#define NH    16
#define DKH   64
#define BATCH 2
#define M_TOT (BATCH * S_LEN)   // 4096

// Scratch
__device__ float g_Q[BATCH * NH * S_LEN * DKH];   // [B,H,S,DK]
__device__ float g_K[BATCH * NH * S_LEN * DKH];
__device__ float g_V[BATCH * NH * S_LEN * DKH];
__device__ float g_X[M_TOT * E_DIM];              // attention out, [B,S,E]

// ---------------------------------------------------------------------------
// Warp-level bf16 MMA (base sm_100 ISA).
// ---------------------------------------------------------------------------
__device__ __forceinline__ void mma16816(float* c, const uint32_t* a, const uint32_t* b) {
    asm volatile(
        "mma.sync.aligned.m16n8k16.row.col.f32.bf16.bf16.f32 "
        "{%0,%1,%2,%3}, {%4,%5,%6,%7}, {%8,%9}, {%0,%1,%2,%3};"
        : "+f"(c[0]), "+f"(c[1]), "+f"(c[2]), "+f"(c[3])
        : "r"(a[0]), "r"(a[1]), "r"(a[2]), "r"(a[3]), "r"(b[0]), "r"(b[1]));
}

__device__ __forceinline__ void split2(float x, float y, uint32_t& hi, uint32_t& lo) {
    __nv_bfloat16 hx = __float2bfloat16_rn(x);
    __nv_bfloat16 hy = __float2bfloat16_rn(y);
    __nv_bfloat16 lx = __float2bfloat16_rn(x - __bfloat162float(hx));
    __nv_bfloat16 ly = __float2bfloat16_rn(y - __bfloat162float(hy));
    hi = (uint32_t)__bfloat16_as_ushort(hx) | ((uint32_t)__bfloat16_as_ushort(hy) << 16);
    lo = (uint32_t)__bfloat16_as_ushort(lx) | ((uint32_t)__bfloat16_as_ushort(ly) << 16);
}

// ---------------------------------------------------------------------------
// GEMM: Y = X @ W^T + bias via HMMA bf16 hi/lo 3-pass.
// Register-prefetch pipeline: chunk kc+1's LDGs issue before chunk kc's MMAs.
// BM=BN=128, BK=32; 256 threads = 8 warps. grid = (8, 32).
// ---------------------------------------------------------------------------
#define PITCH 20

__global__ __launch_bounds__(256) void gemm_mma_kernel(
    const float* __restrict__ X, const float* __restrict__ W,
    const float* __restrict__ bias, float* __restrict__ Y, int splitHeads)
{
    __shared__ uint32_t Ahi[128][PITCH];
    __shared__ uint32_t Alo[128][PITCH];
    __shared__ uint32_t Bhi[128][PITCH];
    __shared__ uint32_t Blo[128][PITCH];

    const int tid  = threadIdx.x;
    const int warp = tid >> 5;
    const int lane = tid & 31;
    const int g = lane >> 2;
    const int t = lane & 3;
    const int wm = warp >> 2;
    const int wn = warp & 3;
    const int m0 = blockIdx.y * 128;
    const int n0 = blockIdx.x * 128;

    // Per-thread load coordinates (4 float4 of X, 4 of W per chunk)
    const int lrow[4] = { (tid + 0)   >> 3, (tid + 256) >> 3,
                          (tid + 512) >> 3, (tid + 768) >> 3 };
    const int lcb [4] = { (tid + 0)   & 7,  (tid + 256) & 7,
                          (tid + 512) & 7,  (tid + 768) & 7 };

    float acc[4][4][4];
    #pragma unroll
    for (int i = 0; i < 4; i++)
        #pragma unroll
        for (int j = 0; j < 4; j++)
            #pragma unroll
            for (int r = 0; r < 4; r++) acc[i][j][r] = 0.f;

    // Prefetch chunk 0
    float4 xr[4], wr[4];
    #pragma unroll
    for (int i = 0; i < 4; i++) {
        xr[i] = *(const float4*)(X + (size_t)(m0 + lrow[i]) * E_DIM + lcb[i] * 4);
        wr[i] = *(const float4*)(W + (size_t)(n0 + lrow[i]) * E_DIM + lcb[i] * 4);
    }

    for (int kc = 0; kc < E_DIM / 32; kc++) {
        __syncthreads();   // previous chunk's MMA consumers done
        #pragma unroll
        for (int i = 0; i < 4; i++) {
            const int row = lrow[i], cb = lcb[i];
            uint32_t h0, l0, h1, l1;
            split2(xr[i].x, xr[i].y, h0, l0);
            split2(xr[i].z, xr[i].w, h1, l1);
            Ahi[row][cb * 2] = h0; Ahi[row][cb * 2 + 1] = h1;
            Alo[row][cb * 2] = l0; Alo[row][cb * 2 + 1] = l1;
            split2(wr[i].x, wr[i].y, h0, l0);
            split2(wr[i].z, wr[i].w, h1, l1);
            Bhi[row][cb * 2] = h0; Bhi[row][cb * 2 + 1] = h1;
            Blo[row][cb * 2] = l0; Blo[row][cb * 2 + 1] = l1;
        }
        __syncthreads();

        // Issue next chunk's loads BEFORE the MMA section (latency hiding)
        if (kc + 1 < E_DIM / 32) {
            const int kt = (kc + 1) * 32;
            #pragma unroll
            for (int i = 0; i < 4; i++) {
                xr[i] = *(const float4*)(X + (size_t)(m0 + lrow[i]) * E_DIM + kt + lcb[i] * 4);
                wr[i] = *(const float4*)(W + (size_t)(n0 + lrow[i]) * E_DIM + kt + lcb[i] * 4);
            }
        }

        #pragma unroll
        for (int ks = 0; ks < 2; ks++) {
            const int kb = ks * 8;
            uint32_t ah[4][4], al[4][4], bh[4][2], bl[4][2];
            #pragma unroll
            for (int mi = 0; mi < 4; mi++) {
                const int r = wm * 64 + mi * 16 + g;
                ah[mi][0] = Ahi[r][kb + t];     ah[mi][1] = Ahi[r + 8][kb + t];
                ah[mi][2] = Ahi[r][kb + t + 4]; ah[mi][3] = Ahi[r + 8][kb + t + 4];
                al[mi][0] = Alo[r][kb + t];     al[mi][1] = Alo[r + 8][kb + t];
                al[mi][2] = Alo[r][kb + t + 4]; al[mi][3] = Alo[r + 8][kb + t + 4];
            }
            #pragma unroll
            for (int ni = 0; ni < 4; ni++) {
                const int r = wn * 32 + ni * 8 + g;
                bh[ni][0] = Bhi[r][kb + t]; bh[ni][1] = Bhi[r][kb + t + 4];
                bl[ni][0] = Blo[r][kb + t]; bl[ni][1] = Blo[r][kb + t + 4];
            }
            #pragma unroll
            for (int mi = 0; mi < 4; mi++)
                #pragma unroll
                for (int ni = 0; ni < 4; ni++) {
                    mma16816(acc[mi][ni], ah[mi], bh[ni]);
                    mma16816(acc[mi][ni], ah[mi], bl[ni]);
                    mma16816(acc[mi][ni], al[mi], bh[ni]);
                }
        }
    }

    #pragma unroll
    for (int mi = 0; mi < 4; mi++) {
        const int mlo = m0 + wm * 64 + mi * 16 + g;
        const int mhi = mlo + 8;
        #pragma unroll
        for (int ni = 0; ni < 4; ni++) {
            const int nb = n0 + wn * 32 + ni * 8 + 2 * t;
            const float bv0 = bias[nb], bv1 = bias[nb + 1];
            const float v00 = acc[mi][ni][0] + bv0;
            const float v01 = acc[mi][ni][1] + bv1;
            const float v10 = acc[mi][ni][2] + bv0;
            const float v11 = acc[mi][ni][3] + bv1;
            if (splitHeads) {
                const int b0 = mlo >> 11, s0 = mlo & (S_LEN - 1);
                const int b1 = mhi >> 11, s1 = mhi & (S_LEN - 1);
                const int h0 = nb >> 6, d0 = nb & 63;
                const int h1 = (nb + 1) >> 6, d1 = (nb + 1) & 63;
                Y[((size_t)((b0 * NH + h0) * S_LEN + s0)) * DKH + d0] = v00;
                Y[((size_t)((b0 * NH + h1) * S_LEN + s0)) * DKH + d1] = v01;
                Y[((size_t)((b1 * NH + h0) * S_LEN + s1)) * DKH + d0] = v10;
                Y[((size_t)((b1 * NH + h1) * S_LEN + s1)) * DKH + d1] = v11;
            } else {
                Y[(size_t)mlo * E_DIM + nb]     = v00;
                Y[(size_t)mlo * E_DIM + nb + 1] = v01;
                Y[(size_t)mhi * E_DIM + nb]     = v10;
                Y[(size_t)mhi * E_DIM + nb + 1] = v11;
            }
        }
    }
}

// ---------------------------------------------------------------------------
// Flash attention via HMMA (unchanged from round 14 — flash improved there).
// BQ=128 (8 warps x 16 rows), BKV=64, causal. launch_bounds(256,2).
// ---------------------------------------------------------------------------
#define FPITCH 36
#define FS_QHI 0
#define FS_QLO 4608
#define FS_KHI 9216
#define FS_KLO 11520
#define FS_VHI 13824
#define FS_VLO 16128
#define FS_TOTAL_B32 18432   // 73728 bytes

__global__ __launch_bounds__(256, 2) void flash_mma_kernel()
{
    extern __shared__ uint32_t fsm[];
    uint32_t (*Qhi)[FPITCH]  = (uint32_t(*)[FPITCH])(fsm + FS_QHI);
    uint32_t (*Qlo)[FPITCH]  = (uint32_t(*)[FPITCH])(fsm + FS_QLO);
    uint32_t (*Khi)[FPITCH]  = (uint32_t(*)[FPITCH])(fsm + FS_KHI);
    uint32_t (*Klo)[FPITCH]  = (uint32_t(*)[FPITCH])(fsm + FS_KLO);
    uint32_t (*Vthi)[FPITCH] = (uint32_t(*)[FPITCH])(fsm + FS_VHI);
    uint32_t (*Vtlo)[FPITCH] = (uint32_t(*)[FPITCH])(fsm + FS_VLO);

    const int tid  = threadIdx.x;
    const int warp = tid >> 5;
    const int lane = tid & 31;
    const int g = lane >> 2;
    const int t = lane & 3;
    const int qt = (int)gridDim.x - 1 - (int)blockIdx.x;
    const int bh = blockIdx.y;
    const int b  = bh >> 4;
    const int h  = bh & 15;

    const float* Qg = g_Q + (size_t)bh * S_LEN * DKH + (size_t)qt * 128 * DKH;
    const float* Kg = g_K + (size_t)bh * S_LEN * DKH;
    const float* Vg = g_V + (size_t)bh * S_LEN * DKH;

    #pragma unroll
    for (int i = 0; i < 8; i++) {
        const int f = tid + i * 256;
        const int r = f >> 4, c4 = f & 15;
        const float4 qv = *(const float4*)(Qg + (size_t)r * DKH + c4 * 4);
        uint32_t h0, l0, h1, l1;
        split2(qv.x, qv.y, h0, l0);
        split2(qv.z, qv.w, h1, l1);
        Qhi[r][2 * c4] = h0; Qhi[r][2 * c4 + 1] = h1;
        Qlo[r][2 * c4] = l0; Qlo[r][2 * c4 + 1] = l1;
    }

    float o[8][4];
    #pragma unroll
    for (int nj = 0; nj < 8; nj++)
        #pragma unroll
        for (int r = 0; r < 4; r++) o[nj][r] = 0.f;
    float m0 = -1e30f, m1 = -1e30f, l0s = 0.f, l1s = 0.f;

    const int ntiles = 2 * qt + 2;
    for (int kt = 0; kt < ntiles; kt++) {
        const int kv0 = kt * 64;

        #pragma unroll
        for (int i = 0; i < 4; i++) {
            const int f = tid + i * 256;
            const int r = f >> 4, c4 = f & 15;
            const float4 kv4 = *(const float4*)(Kg + (size_t)(kv0 + r) * DKH + c4 * 4);
            uint32_t h0, l0, h1, l1;
            split2(kv4.x, kv4.y, h0, l0);
            split2(kv4.z, kv4.w, h1, l1);
            Khi[r][2 * c4] = h0; Khi[r][2 * c4 + 1] = h1;
            Klo[r][2 * c4] = l0; Klo[r][2 * c4 + 1] = l1;
        }
        #pragma unroll
        for (int i = 0; i < 2; i++) {
            const int f = tid + i * 256;
            const int kv2 = f & 31, d4 = f >> 5;
            const float* vp = Vg + (size_t)(kv0 + 2 * kv2) * DKH + d4 * 4;
            const float4 va = *(const float4*)(vp);
            const float4 vb = *(const float4*)(vp + DKH);
            const float aa[4] = {va.x, va.y, va.z, va.w};
            const float bb[4] = {vb.x, vb.y, vb.z, vb.w};
            #pragma unroll
            for (int dd = 0; dd < 4; dd++) {
                uint32_t hh, ll;
                split2(aa[dd], bb[dd], hh, ll);
                Vthi[d4 * 4 + dd][kv2] = hh;
                Vtlo[d4 * 4 + dd][kv2] = ll;
            }
        }
        __syncthreads();

        float sv[8][4];
        #pragma unroll
        for (int ni = 0; ni < 8; ni++)
            #pragma unroll
            for (int j = 0; j < 4; j++) sv[ni][j] = 0.f;

        const int r0 = warp * 16 + g;
        #pragma unroll
        for (int ks = 0; ks < 4; ks++) {
            const int kb = 8 * ks;
            uint32_t aqh[4], aql[4];
            aqh[0] = Qhi[r0][kb + t];     aqh[1] = Qhi[r0 + 8][kb + t];
            aqh[2] = Qhi[r0][kb + t + 4]; aqh[3] = Qhi[r0 + 8][kb + t + 4];
            aql[0] = Qlo[r0][kb + t];     aql[1] = Qlo[r0 + 8][kb + t];
            aql[2] = Qlo[r0][kb + t + 4]; aql[3] = Qlo[r0 + 8][kb + t + 4];
            #pragma unroll
            for (int ni = 0; ni < 8; ni++) {
                uint32_t bkh[2], bkl[2];
                const int kr = 8 * ni + g;
                bkh[0] = Khi[kr][kb + t]; bkh[1] = Khi[kr][kb + t + 4];
                bkl[0] = Klo[kr][kb + t]; bkl[1] = Klo[kr][kb + t + 4];
                mma16816(sv[ni], aqh, bkh);
                mma16816(sv[ni], aqh, bkl);
                mma16816(sv[ni], aql, bkh);
            }
        }

        const bool dm = (kt >= 2 * qt);
        const int cb = (kt - 2 * qt) * 64;
        float mx0 = -1e30f, mx1 = -1e30f;
        #pragma unroll
        for (int ni = 0; ni < 8; ni++) {
            #pragma unroll
            for (int j = 0; j < 4; j++) {
                float s = sv[ni][j] * 0.125f;
                if (dm) {
                    const int c = cb + 8 * ni + 2 * t + (j & 1);
                    const int r = (j < 2) ? r0 : (r0 + 8);
                    if (c > r) s = -1e30f;
                }
                sv[ni][j] = s;
            }
            mx0 = fmaxf(mx0, fmaxf(sv[ni][0], sv[ni][1]));
            mx1 = fmaxf(mx1, fmaxf(sv[ni][2], sv[ni][3]));
        }
        mx0 = fmaxf(mx0, __shfl_xor_sync(0xffffffffu, mx0, 1));
        mx0 = fmaxf(mx0, __shfl_xor_sync(0xffffffffu, mx0, 2));
        mx1 = fmaxf(mx1, __shfl_xor_sync(0xffffffffu, mx1, 1));
        mx1 = fmaxf(mx1, __shfl_xor_sync(0xffffffffu, mx1, 2));

        const float m0n = fmaxf(m0, mx0);
        const float m1n = fmaxf(m1, mx1);
        const float a0 = __expf(m0 - m0n);
        const float a1 = __expf(m1 - m1n);
        float rs0 = 0.f, rs1 = 0.f;
        #pragma unroll
        for (int ni = 0; ni < 8; ni++) {
            sv[ni][0] = __expf(sv[ni][0] - m0n);
            sv[ni][1] = __expf(sv[ni][1] - m0n);
            sv[ni][2] = __expf(sv[ni][2] - m1n);
            sv[ni][3] = __expf(sv[ni][3] - m1n);
            rs0 += sv[ni][0] + sv[ni][1];
            rs1 += sv[ni][2] + sv[ni][3];
        }
        rs0 += __shfl_xor_sync(0xffffffffu, rs0, 1);
        rs0 += __shfl_xor_sync(0xffffffffu, rs0, 2);
        rs1 += __shfl_xor_sync(0xffffffffu, rs1, 1);
        rs1 += __shfl_xor_sync(0xffffffffu, rs1, 2);
        l0s = l0s * a0 + rs0;
        l1s = l1s * a1 + rs1;
        m0 = m0n; m1 = m1n;
        #pragma unroll
        for (int nj = 0; nj < 8; nj++) {
            o[nj][0] *= a0; o[nj][1] *= a0;
            o[nj][2] *= a1; o[nj][3] *= a1;
        }

        #pragma unroll
        for (int ks = 0; ks < 4; ks++) {
            uint32_t aph[4], apl[4];
            split2(sv[2*ks][0],   sv[2*ks][1],   aph[0], apl[0]);
            split2(sv[2*ks][2],   sv[2*ks][3],   aph[1], apl[1]);
            split2(sv[2*ks+1][0], sv[2*ks+1][1], aph[2], apl[2]);
            split2(sv[2*ks+1][2], sv[2*ks+1][3], aph[3], apl[3]);
            const int kb = 8 * ks;
            #pragma unroll
            for (int nj = 0; nj < 8; nj++) {
                const int vr = 8 * nj + g;
                uint32_t bvh[2], bvl[2];
                bvh[0] = Vthi[vr][kb + t]; bvh[1] = Vthi[vr][kb + t + 4];
                bvl[0] = Vtlo[vr][kb + t]; bvl[1] = Vtlo[vr][kb + t + 4];
                mma16816(o[nj], aph, bvh);
                mma16816(o[nj], aph, bvl);
                mma16816(o[nj], apl, bvh);
            }
        }
        __syncthreads();
    }

    const float i0 = 1.f / l0s;
    const float i1 = 1.f / l1s;
    const int s0 = qt * 128 + warp * 16 + g;
    float* X0 = g_X + ((size_t)(b * S_LEN + s0)) * E_DIM + h * DKH;
    float* X1 = X0 + 8 * E_DIM;
    #pragma unroll
    for (int nj = 0; nj < 8; nj++) {
        const int d = 8 * nj + 2 * t;
        *(float2*)(X0 + d) = make_float2(o[nj][0] * i0, o[nj][1] * i0);
        *(float2*)(X1 + d) = make_float2(o[nj][2] * i1, o[nj][3] * i1);
    }
}

// ---------------------------------------------------------------------------
extern "C" void kernel_launch(void* const* d_in, const int* in_sizes, int n_in,
                              void* d_out, int out_size)
{
    const float *q, *k, *v, *wq, *bq, *wk, *bk, *wv, *bv, *wo, *bo;
    if (in_sizes[0] == 1024) {
        // alphabetical: bk bo bq bv key_ mask query value wk wo wq wv
        bk = (const float*)d_in[0];
        bo = (const float*)d_in[1];
        bq = (const float*)d_in[2];
        bv = (const float*)d_in[3];
        k  = (const float*)d_in[4];
        q  = (const float*)d_in[6];
        v  = (const float*)d_in[7];
        wk = (const float*)d_in[8];
        wo = (const float*)d_in[9];
        wq = (const float*)d_in[10];
        wv = (const float*)d_in[11];
    } else {
        // insertion order
        q  = (const float*)d_in[0];
        k  = (const float*)d_in[1];
        v  = (const float*)d_in[2];
        wq = (const float*)d_in[4];
        bq = (const float*)d_in[5];
        wk = (const float*)d_in[6];
        bk = (const float*)d_in[7];
        wv = (const float*)d_in[8];
        bv = (const float*)d_in[9];
        wo = (const float*)d_in[10];
        bo = (const float*)d_in[11];
    }

    float *pQ, *pK, *pV, *pX;
    cudaGetSymbolAddress((void**)&pQ, g_Q);
    cudaGetSymbolAddress((void**)&pK, g_K);
    cudaGetSymbolAddress((void**)&pV, g_V);
    cudaGetSymbolAddress((void**)&pX, g_X);

    const int flash_smem = FS_TOTAL_B32 * (int)sizeof(uint32_t); // 73728
    cudaFuncSetAttribute(flash_mma_kernel,
                         cudaFuncAttributeMaxDynamicSharedMemorySize, flash_smem);

    dim3 gg(E_DIM / 128, M_TOT / 128);   // (8, 32)
    gemm_mma_kernel<<<gg, 256>>>(q, wq, bq, pQ, 1);
    gemm_mma_kernel<<<gg, 256>>>(k, wk, bk, pK, 1);
    gemm_mma_kernel<<<gg, 256>>>(v, wv, bv, pV, 1);

    flash_mma_kernel<<<dim3(S_LEN / 128, BATCH * NH), 256, flash_smem>>>();

    gemm_mma_kernel<<<gg, 256>>>(pX, wo, bo, (float*)d_out, 0);
}

// round 17
// speedup vs baseline: 1.2720x; 1.1061x over previous
#include <cuda_runtime.h>
#include <cuda_bf16.h>
#include <cstdint>
#include <math.h>

// Problem constants
#define S_LEN 2048
#define E_DIM 1024
#define NH    16
#define DKH   64
#define BATCH 2
#define M_TOT (BATCH * S_LEN)   // 4096

// Scratch
__device__ float g_Q[BATCH * NH * S_LEN * DKH];   // [B,H,S,DK]
__device__ float g_K[BATCH * NH * S_LEN * DKH];
__device__ float g_V[BATCH * NH * S_LEN * DKH];
__device__ float g_X[M_TOT * E_DIM];              // attention out, [B,S,E]

// ---------------------------------------------------------------------------
// Warp-level bf16 MMA (base sm_100 ISA).
// ---------------------------------------------------------------------------
__device__ __forceinline__ void mma16816(float* c, const uint32_t* a, const uint32_t* b) {
    asm volatile(
        "mma.sync.aligned.m16n8k16.row.col.f32.bf16.bf16.f32 "
        "{%0,%1,%2,%3}, {%4,%5,%6,%7}, {%8,%9}, {%0,%1,%2,%3};"
        : "+f"(c[0]), "+f"(c[1]), "+f"(c[2]), "+f"(c[3])
        : "r"(a[0]), "r"(a[1]), "r"(a[2]), "r"(a[3]), "r"(b[0]), "r"(b[1]));
}

__device__ __forceinline__ void split2(float x, float y, uint32_t& hi, uint32_t& lo) {
    __nv_bfloat16 hx = __float2bfloat16_rn(x);
    __nv_bfloat16 hy = __float2bfloat16_rn(y);
    __nv_bfloat16 lx = __float2bfloat16_rn(x - __bfloat162float(hx));
    __nv_bfloat16 ly = __float2bfloat16_rn(y - __bfloat162float(hy));
    hi = (uint32_t)__bfloat16_as_ushort(hx) | ((uint32_t)__bfloat16_as_ushort(hy) << 16);
    lo = (uint32_t)__bfloat16_as_ushort(lx) | ((uint32_t)__bfloat16_as_ushort(ly) << 16);
}

// ---------------------------------------------------------------------------
// GEMM: Y = X @ W^T + bias via HMMA bf16 hi/lo 3-pass.
// ROUND-13 VERSION (no prefetch) — measured ~98 us/launch (~263 TF/s, at the
// HMMA ceiling). Do not touch.
// BM=BN=128, BK=32; 256 threads = 8 warps. grid = (8, 32).
// ---------------------------------------------------------------------------
#define PITCH 20

__global__ __launch_bounds__(256) void gemm_mma_kernel(
    const float* __restrict__ X, const float* __restrict__ W,
    const float* __restrict__ bias, float* __restrict__ Y, int splitHeads)
{
    __shared__ uint32_t Ahi[128][PITCH];
    __shared__ uint32_t Alo[128][PITCH];
    __shared__ uint32_t Bhi[128][PITCH];
    __shared__ uint32_t Blo[128][PITCH];

    const int tid  = threadIdx.x;
    const int warp = tid >> 5;
    const int lane = tid & 31;
    const int g = lane >> 2;
    const int t = lane & 3;
    const int wm = warp >> 2;
    const int wn = warp & 3;
    const int m0 = blockIdx.y * 128;
    const int n0 = blockIdx.x * 128;

    float acc[4][4][4];
    #pragma unroll
    for (int i = 0; i < 4; i++)
        #pragma unroll
        for (int j = 0; j < 4; j++)
            #pragma unroll
            for (int r = 0; r < 4; r++) acc[i][j][r] = 0.f;

    for (int kc = 0; kc < E_DIM / 32; kc++) {
        const int kt = kc * 32;
        #pragma unroll
        for (int i = 0; i < 4; i++) {
            const int f   = tid + i * 256;
            const int row = f >> 3;
            const int cb  = f & 7;
            const float4 xv = *(const float4*)(X + (size_t)(m0 + row) * E_DIM + kt + cb * 4);
            const float4 wv = *(const float4*)(W + (size_t)(n0 + row) * E_DIM + kt + cb * 4);
            uint32_t h0, l0, h1, l1;
            split2(xv.x, xv.y, h0, l0);
            split2(xv.z, xv.w, h1, l1);
            Ahi[row][cb * 2] = h0; Ahi[row][cb * 2 + 1] = h1;
            Alo[row][cb * 2] = l0; Alo[row][cb * 2 + 1] = l1;
            split2(wv.x, wv.y, h0, l0);
            split2(wv.z, wv.w, h1, l1);
            Bhi[row][cb * 2] = h0; Bhi[row][cb * 2 + 1] = h1;
            Blo[row][cb * 2] = l0; Blo[row][cb * 2 + 1] = l1;
        }
        __syncthreads();

        #pragma unroll
        for (int ks = 0; ks < 2; ks++) {
            const int kb = ks * 8;
            uint32_t ah[4][4], al[4][4], bh[4][2], bl[4][2];
            #pragma unroll
            for (int mi = 0; mi < 4; mi++) {
                const int r = wm * 64 + mi * 16 + g;
                ah[mi][0] = Ahi[r][kb + t];     ah[mi][1] = Ahi[r + 8][kb + t];
                ah[mi][2] = Ahi[r][kb + t + 4]; ah[mi][3] = Ahi[r + 8][kb + t + 4];
                al[mi][0] = Alo[r][kb + t];     al[mi][1] = Alo[r + 8][kb + t];
                al[mi][2] = Alo[r][kb + t + 4]; al[mi][3] = Alo[r + 8][kb + t + 4];
            }
            #pragma unroll
            for (int ni = 0; ni < 4; ni++) {
                const int r = wn * 32 + ni * 8 + g;
                bh[ni][0] = Bhi[r][kb + t]; bh[ni][1] = Bhi[r][kb + t + 4];
                bl[ni][0] = Blo[r][kb + t]; bl[ni][1] = Blo[r][kb + t + 4];
            }
            #pragma unroll
            for (int mi = 0; mi < 4; mi++)
                #pragma unroll
                for (int ni = 0; ni < 4; ni++) {
                    mma16816(acc[mi][ni], ah[mi], bh[ni]);
                    mma16816(acc[mi][ni], ah[mi], bl[ni]);
                    mma16816(acc[mi][ni], al[mi], bh[ni]);
                }
        }
        __syncthreads();
    }

    #pragma unroll
    for (int mi = 0; mi < 4; mi++) {
        const int mlo = m0 + wm * 64 + mi * 16 + g;
        const int mhi = mlo + 8;
        #pragma unroll
        for (int ni = 0; ni < 4; ni++) {
            const int nb = n0 + wn * 32 + ni * 8 + 2 * t;
            const float bv0 = bias[nb], bv1 = bias[nb + 1];
            const float v00 = acc[mi][ni][0] + bv0;
            const float v01 = acc[mi][ni][1] + bv1;
            const float v10 = acc[mi][ni][2] + bv0;
            const float v11 = acc[mi][ni][3] + bv1;
            if (splitHeads) {
                const int b0 = mlo >> 11, s0 = mlo & (S_LEN - 1);
                const int b1 = mhi >> 11, s1 = mhi & (S_LEN - 1);
                const int h0 = nb >> 6, d0 = nb & 63;
                const int h1 = (nb + 1) >> 6, d1 = (nb + 1) & 63;
                Y[((size_t)((b0 * NH + h0) * S_LEN + s0)) * DKH + d0] = v00;
                Y[((size_t)((b0 * NH + h1) * S_LEN + s0)) * DKH + d1] = v01;
                Y[((size_t)((b1 * NH + h0) * S_LEN + s1)) * DKH + d0] = v10;
                Y[((size_t)((b1 * NH + h1) * S_LEN + s1)) * DKH + d1] = v11;
            } else {
                Y[(size_t)mlo * E_DIM + nb]     = v00;
                Y[(size_t)mlo * E_DIM + nb + 1] = v01;
                Y[(size_t)mhi * E_DIM + nb]     = v10;
                Y[(size_t)mhi * E_DIM + nb + 1] = v11;
            }
        }
    }
}

// ---------------------------------------------------------------------------
// Flash attention via HMMA (round-15 version, measured 322.5 us).
// BQ=128 (8 warps x 16 rows), BKV=64, causal. launch_bounds(256,2).
// ---------------------------------------------------------------------------
#define FPITCH 36
#define FS_QHI 0
#define FS_QLO 4608
#define FS_KHI 9216
#define FS_KLO 11520
#define FS_VHI 13824
#define FS_VLO 16128
#define FS_TOTAL_B32 18432   // 73728 bytes

__global__ __launch_bounds__(256, 2) void flash_mma_kernel()
{
    extern __shared__ uint32_t fsm[];
    uint32_t (*Qhi)[FPITCH]  = (uint32_t(*)[FPITCH])(fsm + FS_QHI);
    uint32_t (*Qlo)[FPITCH]  = (uint32_t(*)[FPITCH])(fsm + FS_QLO);
    uint32_t (*Khi)[FPITCH]  = (uint32_t(*)[FPITCH])(fsm + FS_KHI);
    uint32_t (*Klo)[FPITCH]  = (uint32_t(*)[FPITCH])(fsm + FS_KLO);
    uint32_t (*Vthi)[FPITCH] = (uint32_t(*)[FPITCH])(fsm + FS_VHI);
    uint32_t (*Vtlo)[FPITCH] = (uint32_t(*)[FPITCH])(fsm + FS_VLO);

    const int tid  = threadIdx.x;
    const int warp = tid >> 5;
    const int lane = tid & 31;
    const int g = lane >> 2;
    const int t = lane & 3;
    const int qt = (int)gridDim.x - 1 - (int)blockIdx.x;
    const int bh = blockIdx.y;
    const int b  = bh >> 4;
    const int h  = bh & 15;

    const float* Qg = g_Q + (size_t)bh * S_LEN * DKH + (size_t)qt * 128 * DKH;
    const float* Kg = g_K + (size_t)bh * S_LEN * DKH;
    const float* Vg = g_V + (size_t)bh * S_LEN * DKH;

    #pragma unroll
    for (int i = 0; i < 8; i++) {
        const int f = tid + i * 256;
        const int r = f >> 4, c4 = f & 15;
        const float4 qv = *(const float4*)(Qg + (size_t)r * DKH + c4 * 4);
        uint32_t h0, l0, h1, l1;
        split2(qv.x, qv.y, h0, l0);
        split2(qv.z, qv.w, h1, l1);
        Qhi[r][2 * c4] = h0; Qhi[r][2 * c4 + 1] = h1;
        Qlo[r][2 * c4] = l0; Qlo[r][2 * c4 + 1] = l1;
    }

    float o[8][4];
    #pragma unroll
    for (int nj = 0; nj < 8; nj++)
        #pragma unroll
        for (int r = 0; r < 4; r++) o[nj][r] = 0.f;
    float m0 = -1e30f, m1 = -1e30f, l0s = 0.f, l1s = 0.f;

    const int ntiles = 2 * qt + 2;
    for (int kt = 0; kt < ntiles; kt++) {
        const int kv0 = kt * 64;

        #pragma unroll
        for (int i = 0; i < 4; i++) {
            const int f = tid + i * 256;
            const int r = f >> 4, c4 = f & 15;
            const float4 kv4 = *(const float4*)(Kg + (size_t)(kv0 + r) * DKH + c4 * 4);
            uint32_t h0, l0, h1, l1;
            split2(kv4.x, kv4.y, h0, l0);
            split2(kv4.z, kv4.w, h1, l1);
            Khi[r][2 * c4] = h0; Khi[r][2 * c4 + 1] = h1;
            Klo[r][2 * c4] = l0; Klo[r][2 * c4 + 1] = l1;
        }
        #pragma unroll
        for (int i = 0; i < 2; i++) {
            const int f = tid + i * 256;
            const int kv2 = f & 31, d4 = f >> 5;
            const float* vp = Vg + (size_t)(kv0 + 2 * kv2) * DKH + d4 * 4;
            const float4 va = *(const float4*)(vp);
            const float4 vb = *(const float4*)(vp + DKH);
            const float aa[4] = {va.x, va.y, va.z, va.w};
            const float bb[4] = {vb.x, vb.y, vb.z, vb.w};
            #pragma unroll
            for (int dd = 0; dd < 4; dd++) {
                uint32_t hh, ll;
                split2(aa[dd], bb[dd], hh, ll);
                Vthi[d4 * 4 + dd][kv2] = hh;
                Vtlo[d4 * 4 + dd][kv2] = ll;
            }
        }
        __syncthreads();

        float sv[8][4];
        #pragma unroll
        for (int ni = 0; ni < 8; ni++)
            #pragma unroll
            for (int j = 0; j < 4; j++) sv[ni][j] = 0.f;

        const int r0 = warp * 16 + g;
        #pragma unroll
        for (int ks = 0; ks < 4; ks++) {
            const int kb = 8 * ks;
            uint32_t aqh[4], aql[4];
            aqh[0] = Qhi[r0][kb + t];     aqh[1] = Qhi[r0 + 8][kb + t];
            aqh[2] = Qhi[r0][kb + t + 4]; aqh[3] = Qhi[r0 + 8][kb + t + 4];
            aql[0] = Qlo[r0][kb + t];     aql[1] = Qlo[r0 + 8][kb + t];
            aql[2] = Qlo[r0][kb + t + 4]; aql[3] = Qlo[r0 + 8][kb + t + 4];
            #pragma unroll
            for (int ni = 0; ni < 8; ni++) {
                uint32_t bkh[2], bkl[2];
                const int kr = 8 * ni + g;
                bkh[0] = Khi[kr][kb + t]; bkh[1] = Khi[kr][kb + t + 4];
                bkl[0] = Klo[kr][kb + t]; bkl[1] = Klo[kr][kb + t + 4];
                mma16816(sv[ni], aqh, bkh);
                mma16816(sv[ni], aqh, bkl);
                mma16816(sv[ni], aql, bkh);
            }
        }

        const bool dm = (kt >= 2 * qt);
        const int cb = (kt - 2 * qt) * 64;
        float mx0 = -1e30f, mx1 = -1e30f;
        #pragma unroll
        for (int ni = 0; ni < 8; ni++) {
            #pragma unroll
            for (int j = 0; j < 4; j++) {
                float s = sv[ni][j] * 0.125f;
                if (dm) {
                    const int c = cb + 8 * ni + 2 * t + (j & 1);
                    const int r = (j < 2) ? r0 : (r0 + 8);
                    if (c > r) s = -1e30f;
                }
                sv[ni][j] = s;
            }
            mx0 = fmaxf(mx0, fmaxf(sv[ni][0], sv[ni][1]));
            mx1 = fmaxf(mx1, fmaxf(sv[ni][2], sv[ni][3]));
        }
        mx0 = fmaxf(mx0, __shfl_xor_sync(0xffffffffu, mx0, 1));
        mx0 = fmaxf(mx0, __shfl_xor_sync(0xffffffffu, mx0, 2));
        mx1 = fmaxf(mx1, __shfl_xor_sync(0xffffffffu, mx1, 1));
        mx1 = fmaxf(mx1, __shfl_xor_sync(0xffffffffu, mx1, 2));

        const float m0n = fmaxf(m0, mx0);
        const float m1n = fmaxf(m1, mx1);
        const float a0 = __expf(m0 - m0n);
        const float a1 = __expf(m1 - m1n);
        float rs0 = 0.f, rs1 = 0.f;
        #pragma unroll
        for (int ni = 0; ni < 8; ni++) {
            sv[ni][0] = __expf(sv[ni][0] - m0n);
            sv[ni][1] = __expf(sv[ni][1] - m0n);
            sv[ni][2] = __expf(sv[ni][2] - m1n);
            sv[ni][3] = __expf(sv[ni][3] - m1n);
            rs0 += sv[ni][0] + sv[ni][1];
            rs1 += sv[ni][2] + sv[ni][3];
        }
        rs0 += __shfl_xor_sync(0xffffffffu, rs0, 1);
        rs0 += __shfl_xor_sync(0xffffffffu, rs0, 2);
        rs1 += __shfl_xor_sync(0xffffffffu, rs1, 1);
        rs1 += __shfl_xor_sync(0xffffffffu, rs1, 2);
        l0s = l0s * a0 + rs0;
        l1s = l1s * a1 + rs1;
        m0 = m0n; m1 = m1n;
        #pragma unroll
        for (int nj = 0; nj < 8; nj++) {
            o[nj][0] *= a0; o[nj][1] *= a0;
            o[nj][2] *= a1; o[nj][3] *= a1;
        }

        #pragma unroll
        for (int ks = 0; ks < 4; ks++) {
            uint32_t aph[4], apl[4];
            split2(sv[2*ks][0],   sv[2*ks][1],   aph[0], apl[0]);
            split2(sv[2*ks][2],   sv[2*ks][3],   aph[1], apl[1]);
            split2(sv[2*ks+1][0], sv[2*ks+1][1], aph[2], apl[2]);
            split2(sv[2*ks+1][2], sv[2*ks+1][3], aph[3], apl[3]);
            const int kb = 8 * ks;
            #pragma unroll
            for (int nj = 0; nj < 8; nj++) {
                const int vr = 8 * nj + g;
                uint32_t bvh[2], bvl[2];
                bvh[0] = Vthi[vr][kb + t]; bvh[1] = Vthi[vr][kb + t + 4];
                bvl[0] = Vtlo[vr][kb + t]; bvl[1] = Vtlo[vr][kb + t + 4];
                mma16816(o[nj], aph, bvh);
                mma16816(o[nj], aph, bvl);
                mma16816(o[nj], apl, bvh);
            }
        }
        __syncthreads();
    }

    const float i0 = 1.f / l0s;
    const float i1 = 1.f / l1s;
    const int s0 = qt * 128 + warp * 16 + g;
    float* X0 = g_X + ((size_t)(b * S_LEN + s0)) * E_DIM + h * DKH;
    float* X1 = X0 + 8 * E_DIM;
    #pragma unroll
    for (int nj = 0; nj < 8; nj++) {
        const int d = 8 * nj + 2 * t;
        *(float2*)(X0 + d) = make_float2(o[nj][0] * i0, o[nj][1] * i0);
        *(float2*)(X1 + d) = make_float2(o[nj][2] * i1, o[nj][3] * i1);
    }
}

// ---------------------------------------------------------------------------
extern "C" void kernel_launch(void* const* d_in, const int* in_sizes, int n_in,
                              void* d_out, int out_size)
{
    const float *q, *k, *v, *wq, *bq, *wk, *bk, *wv, *bv, *wo, *bo;
    if (in_sizes[0] == 1024) {
        // alphabetical: bk bo bq bv key_ mask query value wk wo wq wv
        bk = (const float*)d_in[0];
        bo = (const float*)d_in[1];
        bq = (const float*)d_in[2];
        bv = (const float*)d_in[3];
        k  = (const float*)d_in[4];
        q  = (const float*)d_in[6];
        v  = (const float*)d_in[7];
        wk = (const float*)d_in[8];
        wo = (const float*)d_in[9];
        wq = (const float*)d_in[10];
        wv = (const float*)d_in[11];
    } else {
        // insertion order
        q  = (const float*)d_in[0];
        k  = (const float*)d_in[1];
        v  = (const float*)d_in[2];
        wq = (const float*)d_in[4];
        bq = (const float*)d_in[5];
        wk = (const float*)d_in[6];
        bk = (const float*)d_in[7];
        wv = (const float*)d_in[8];
        bv = (const float*)d_in[9];
        wo = (const float*)d_in[10];
        bo = (const float*)d_in[11];
    }

    float *pQ, *pK, *pV, *pX;
    cudaGetSymbolAddress((void**)&pQ, g_Q);
    cudaGetSymbolAddress((void**)&pK, g_K);
    cudaGetSymbolAddress((void**)&pV, g_V);
    cudaGetSymbolAddress((void**)&pX, g_X);

    const int flash_smem = FS_TOTAL_B32 * (int)sizeof(uint32_t); // 73728
    cudaFuncSetAttribute(flash_mma_kernel,
                         cudaFuncAttributeMaxDynamicSharedMemorySize, flash_smem);

    dim3 gg(E_DIM / 128, M_TOT / 128);   // (8, 32)
    gemm_mma_kernel<<<gg, 256>>>(q, wq, bq, pQ, 1);
    gemm_mma_kernel<<<gg, 256>>>(k, wk, bk, pK, 1);
    gemm_mma_kernel<<<gg, 256>>>(v, wv, bv, pV, 1);

    flash_mma_kernel<<<dim3(S_LEN / 128, BATCH * NH), 256, flash_smem>>>();

    gemm_mma_kernel<<<gg, 256>>>(pX, wo, bo, (float*)d_out, 0);
}